// round 9
// baseline (speedup 1.0000x reference)
#include <cuda_runtime.h>
#include <stdint.h>

// ---------------------------------------------------------------------------
// ImaginationMPCV2 — bit-exact to jax on Grace CPU (aarch64): XLA:CPU strict
// middle-end + backend FPOpFusion::Fast (aarch64 fmadd fusion), trig = glibc
// optimized-routines sinf/cosf (TOINT_INTRINSICS), ported bit-exactly.
//
// R9 perf changes (bit-preserving per trajectory):
//  * TWO independent trajectories per thread -> two interleaved dependency
//    chains hide the ~50-60 cyc DFMA latency (R8 was latency-bound:
//    issue 10.3%, ~65-cyc stalls/warp).
//  * __launch_bounds__(128, 4): register budget up to 128 so both chains'
//    trig evals stay concurrently in flight.
//  * Removed the unreachable |x|>=120 fallback: loop body is now fully
//    branchless straight-line code.
// ---------------------------------------------------------------------------

#define EPS_F          1e-5f
#define TWO_EPS_F      2e-5f
#define DT_F           0.02f
#define HALF_DT_F      0.01f
#define HALF_DT_FR_F   0.001f
#define PI_F           3.14159265358979323846f
#define TWO_PI_F       6.28318530717958647692f
#define T_STEPS        100

// ---- glibc sincosf constants (optimized-routines, table entry 0) ----
#define HPI_INV_D  0x1.45F306DC9C883p-1   // 2/pi
#define HPI_D      0x1.921FB54442D18p0    // pi/2
#define S1_D      -0x1.555545995a603p-3
#define S2_D       0x1.1107605230bc4p-7
#define S3_D      -0x1.994eb3774cf24p-13
#define C0_D       0x1p0
#define C1_D      -0x1.ffffffd0c621cp-2
#define C2_D       0x1.55553e1068f19p-5
#define C3_D      -0x1.6c087e89a359dp-10
#define C4_D       0x1.99343027bf8c3p-16

__device__ __forceinline__ float sinpoly_mag(double xr, double x2)
{
    double x3 = xr * x2;
    double s1 = fma(x2, S3_D, S2_D);
    double x7 = x3 * x2;
    double s  = fma(x3, S1_D, xr);
    return (float)fma(x7, s1, s);
}

__device__ __forceinline__ float cospoly_mag(double x2)
{
    double x4 = x2 * x2;
    double c2 = fma(x2, C4_D, C3_D);
    double c1 = fma(x2, C1_D, C0_D);
    double x6 = x4 * x2;
    double c  = fma(x4, C2_D, c1);
    return (float)fma(x6, c2, c);
}

__device__ __forceinline__ float sign_xor(float v, uint32_t bit31)
{
    return __uint_as_float(__float_as_uint(v) ^ bit31);
}

// Branchless glibc sinf+cosf, valid (bit-exact) for |y| < 120 — guaranteed
// for this bounded-energy system. For |y| < pi/4 the reduction yields n=0,
// xr=x, reproducing the glibc fast paths bitwise (incl. tiny |y| < 2^-12).
__device__ __forceinline__ void glibc_sincosf(float y, float* so, float* co)
{
    double x = (double)y;

    double r  = x * HPI_INV_D;
    int    n  = __double2int_rn(r);   // fcvtns (ties-to-even)
    double rr = (double)n;
    double xr = fma(-rr, HPI_D, x);

    double x2 = xr * xr;
    float  sm = sinpoly_mag(xr, x2);
    float  cm = cospoly_mag(x2);

    int odd = n & 1;
    float smag = odd ? cm : sm;
    float cmag = odd ? sm : cm;
    *so = sign_xor(smag, ((uint32_t)(n & 2)) << 30);
    *co = sign_xor(cmag, ((uint32_t)((n + 1) & 2)) << 30);
}

__device__ __forceinline__ float glibc_cosf(float y)
{
    double x = (double)y;

    double r  = x * HPI_INV_D;
    int    n  = __double2int_rn(r);
    double rr = (double)n;
    double xr = fma(-rr, HPI_D, x);

    double x2 = xr * xr;
    float  sm = sinpoly_mag(xr, x2);
    float  cm = cospoly_mag(x2);

    float cmag = (n & 1) ? sm : cm;
    return sign_xor(cmag, ((uint32_t)((n + 1) & 2)) << 30);
}

// ---- Hamiltonian with aarch64-backend fusion pattern ----
__device__ __forceinline__ float ham_f(float p1, float p2,
                                       float s, float c,
                                       float c1, float c2)
{
    float denom = __fmul_rn(2.0f, fmaf(s, s, 1.0f));
    float t2    = __fmul_rn(2.0f, __fmul_rn(p2, p2));
    float t3    = __fmul_rn(__fmul_rn(2.0f, p1), p2);
    float num   = fmaf(-t3, c, fmaf(p1, p1, t2));
    float T     = __fdiv_rn(num, denom);
    float vw    = __fadd_rn(__fsub_rn(1.0f, c1), __fsub_rn(1.0f, c2));
    return fmaf(10.0f, vw, T);
}

__device__ __forceinline__ void grads_q(float q1, float q2, float p1, float p2,
                                        float c1b, float c2b,
                                        float* g1, float* g2)
{
    float sa, ca, sbq, cbq, sc, cc, sd, cd;

    float q1p = __fadd_rn(q1, EPS_F);
    float q1m = __fsub_rn(q1, EPS_F);
    float q2p = __fadd_rn(q2, EPS_F);
    float q2m = __fsub_rn(q2, EPS_F);

    glibc_sincosf(__fsub_rn(q1p, q2), &sa, &ca);
    glibc_sincosf(__fsub_rn(q1m, q2), &sbq, &cbq);
    glibc_sincosf(__fsub_rn(q1, q2p), &sc, &cc);
    glibc_sincosf(__fsub_rn(q1, q2m), &sd, &cd);
    float cq1p = glibc_cosf(q1p);
    float cq1m = glibc_cosf(q1m);
    float cq2p = glibc_cosf(q2p);
    float cq2m = glibc_cosf(q2m);

    float Hp1 = ham_f(p1, p2, sa, ca, cq1p, c2b);
    float Hm1 = ham_f(p1, p2, sbq, cbq, cq1m, c2b);
    *g1 = __fdiv_rn(__fsub_rn(Hp1, Hm1), TWO_EPS_F);

    float Hp2 = ham_f(p1, p2, sc, cc, c1b, cq2p);
    float Hm2 = ham_f(p1, p2, sd, cd, c1b, cq2m);
    *g2 = __fdiv_rn(__fsub_rn(Hp2, Hm2), TWO_EPS_F);
}

__device__ __forceinline__ void grads_p(float p1, float p2,
                                        float s, float c, float c1, float c2,
                                        float* g1, float* g2)
{
    float Hp1 = ham_f(__fadd_rn(p1, EPS_F), p2, s, c, c1, c2);
    float Hm1 = ham_f(__fsub_rn(p1, EPS_F), p2, s, c, c1, c2);
    *g1 = __fdiv_rn(__fsub_rn(Hp1, Hm1), TWO_EPS_F);

    float Hp2 = ham_f(p1, __fadd_rn(p2, EPS_F), s, c, c1, c2);
    float Hm2 = ham_f(p1, __fsub_rn(p2, EPS_F), s, c, c1, c2);
    *g2 = __fdiv_rn(__fsub_rn(Hp2, Hm2), TWO_EPS_F);
}

__device__ __forceinline__ float anorm(float th)
{
    float t = __fadd_rn(th, PI_F);
    float r = fmodf(t, TWO_PI_F);
    if (r < 0.0f) r = __fadd_rn(r, TWO_PI_F);
    return __fsub_rn(r, PI_F);
}

__global__ void __launch_bounds__(128, 4)
imagination_mpc_kernel(const float* __restrict__ q0,
                       const float* __restrict__ p0,
                       const float* __restrict__ actions,
                       const float* __restrict__ target,
                       float* __restrict__ out,
                       int n)
{
    int h = n >> 1;                       // trajectories per stream
    int i = blockIdx.x * blockDim.x + threadIdx.x;
    if (i >= h) return;

    int idx[2] = { i, i + h };            // two independent trajectories

    float q1[2], q2[2], p1[2], p2[2];
    float sb[2], cb[2], c1b[2], c2b[2];
    float run[2];
    const float* arow[2];

    float tg1 = target[0], tg2 = target[1];

#pragma unroll
    for (int j = 0; j < 2; j++) {
        q1[j] = q0[2 * idx[j]];     q2[j] = q0[2 * idx[j] + 1];
        p1[j] = p0[2 * idx[j]];     p2[j] = p0[2 * idx[j] + 1];
        arow[j] = actions + (long long)idx[j] * T_STEPS;
        glibc_sincosf(__fsub_rn(q1[j], q2[j]), &sb[j], &cb[j]);
        c1b[j] = glibc_cosf(q1[j]);
        c2b[j] = glibc_cosf(q2[j]);
        run[j] = 0.0f;
    }

#pragma unroll 1
    for (int t = 0; t < T_STEPS; t++) {
        float a[2];
#pragma unroll
        for (int j = 0; j < 2; j++) a[j] = __ldg(&arow[j][t]);

        // ---- running cost ----
#pragma unroll
        for (int j = 0; j < 2; j++) {
            float e1  = anorm(__fsub_rn(q1[j], tg1));
            float e2  = anorm(__fsub_rn(q2[j], tg2));
            float pos = fmaf(e1, e1, __fmul_rn(e2, e2));
            float vel = fmaf(p1[j], p1[j], __fmul_rn(p2[j], p2[j]));
            float asq = __fmul_rn(a[j], a[j]);
            float term_t = fmaf(0.01f, asq, __fadd_rn(pos, vel));
            run[j] = __fadd_rn(run[j], term_t);
        }

        // ---- symplectic step (phases interleaved across both chains) ----
        float gq1[2], gq2[2], gp1[2], gp2[2];
#pragma unroll
        for (int j = 0; j < 2; j++)
            grads_q(q1[j], q2[j], p1[j], p2[j], c1b[j], c2b[j], &gq1[j], &gq2[j]);
#pragma unroll
        for (int j = 0; j < 2; j++)
            grads_p(p1[j], p2[j], sb[j], cb[j], c1b[j], c2b[j], &gp1[j], &gp2[j]);

        float ph1[2], ph2[2];
#pragma unroll
        for (int j = 0; j < 2; j++) {
            ph1[j] = fmaf(-HALF_DT_FR_F, gp1[j], fmaf(-HALF_DT_F, gq1[j], p1[j]));
            ph2[j] = fmaf(-HALF_DT_FR_F, gp2[j], fmaf(-HALF_DT_F, gq2[j], p2[j]));
        }

        float gm1[2], gm2[2];
#pragma unroll
        for (int j = 0; j < 2; j++)
            grads_p(ph1[j], ph2[j], sb[j], cb[j], c1b[j], c2b[j], &gm1[j], &gm2[j]);

        float qn1[2], qn2[2];
#pragma unroll
        for (int j = 0; j < 2; j++) {
            qn1[j] = fmaf(DT_F, gm1[j], q1[j]);
            qn2[j] = fmaf(DT_F, gm2[j], q2[j]);
        }

        float sbn[2], cbn[2], c1n[2], c2n[2];
#pragma unroll
        for (int j = 0; j < 2; j++) {
            glibc_sincosf(__fsub_rn(qn1[j], qn2[j]), &sbn[j], &cbn[j]);
            c1n[j] = glibc_cosf(qn1[j]);
            c2n[j] = glibc_cosf(qn2[j]);
        }

        float hq1[2], hq2[2], hp1[2], hp2[2];
#pragma unroll
        for (int j = 0; j < 2; j++)
            grads_q(qn1[j], qn2[j], ph1[j], ph2[j], c1n[j], c2n[j], &hq1[j], &hq2[j]);
#pragma unroll
        for (int j = 0; j < 2; j++)
            grads_p(ph1[j], ph2[j], sbn[j], cbn[j], c1n[j], c2n[j], &hp1[j], &hp2[j]);

#pragma unroll
        for (int j = 0; j < 2; j++) {
            float pn1 = fmaf(-HALF_DT_FR_F, hp1[j], fmaf(-HALF_DT_F, hq1[j], ph1[j]));
            float pn2 = fmaf(-HALF_DT_FR_F, hp2[j], fmaf(-HALF_DT_F, hq2[j], ph2[j]));
            pn2 = fmaf(a[j], DT_F, pn2);

            q1[j] = qn1[j]; q2[j] = qn2[j]; p1[j] = pn1; p2[j] = pn2;
            sb[j] = sbn[j]; cb[j] = cbn[j]; c1b[j] = c1n[j]; c2b[j] = c2n[j];
        }
    }

    // ---- terminal cost ----
#pragma unroll
    for (int j = 0; j < 2; j++) {
        float e1 = anorm(__fsub_rn(q1[j], tg1));
        float e2 = anorm(__fsub_rn(q2[j], tg2));
        float pos_sum = fmaf(e2, e2, __fmul_rn(e1, e1));
        float vel_sum = fmaf(p2[j], p2[j], __fmul_rn(p1[j], p1[j]));
        float term = fmaf(10.0f, pos_sum, vel_sum);
        out[idx[j]] = __fadd_rn(run[j], term);
    }
}

extern "C" void kernel_launch(void* const* d_in, const int* in_sizes, int n_in,
                              void* d_out, int out_size)
{
    const float* q0      = (const float*)d_in[0];
    const float* p0      = (const float*)d_in[1];
    const float* actions = (const float*)d_in[2];
    const float* target  = (const float*)d_in[3];
    float* out = (float*)d_out;

    int n = in_sizes[0] / 2;
    int h = n / 2;                         // two trajectories per thread
    int threads = 128;
    int blocks = (h + threads - 1) / threads;
    imagination_mpc_kernel<<<blocks, threads>>>(q0, p0, actions, target, out, n);
}

// round 10
// speedup vs baseline: 1.0011x; 1.0011x over previous
#include <cuda_runtime.h>
#include <stdint.h>

// ---------------------------------------------------------------------------
// ImaginationMPCV2 — bit-exact to jax on Grace CPU (aarch64): XLA:CPU strict
// middle-end + backend FPOpFusion::Fast (aarch64 fmadd fusion), trig = glibc
// optimized-routines sinf/cosf (TOINT_INTRINSICS), ported bit-exactly.
//
// R9 perf changes (bit-preserving per trajectory):
//  * TWO independent trajectories per thread -> two interleaved dependency
//    chains hide the ~50-60 cyc DFMA latency (R8 was latency-bound:
//    issue 10.3%, ~65-cyc stalls/warp).
//  * __launch_bounds__(128, 4): register budget up to 128 so both chains'
//    trig evals stay concurrently in flight.
//  * Removed the unreachable |x|>=120 fallback: loop body is now fully
//    branchless straight-line code.
// ---------------------------------------------------------------------------

#define EPS_F          1e-5f
#define TWO_EPS_F      2e-5f
#define DT_F           0.02f
#define HALF_DT_F      0.01f
#define HALF_DT_FR_F   0.001f
#define PI_F           3.14159265358979323846f
#define TWO_PI_F       6.28318530717958647692f
#define T_STEPS        100

// ---- glibc sincosf constants (optimized-routines, table entry 0) ----
#define HPI_INV_D  0x1.45F306DC9C883p-1   // 2/pi
#define HPI_D      0x1.921FB54442D18p0    // pi/2
#define S1_D      -0x1.555545995a603p-3
#define S2_D       0x1.1107605230bc4p-7
#define S3_D      -0x1.994eb3774cf24p-13
#define C0_D       0x1p0
#define C1_D      -0x1.ffffffd0c621cp-2
#define C2_D       0x1.55553e1068f19p-5
#define C3_D      -0x1.6c087e89a359dp-10
#define C4_D       0x1.99343027bf8c3p-16

__device__ __forceinline__ float sinpoly_mag(double xr, double x2)
{
    double x3 = xr * x2;
    double s1 = fma(x2, S3_D, S2_D);
    double x7 = x3 * x2;
    double s  = fma(x3, S1_D, xr);
    return (float)fma(x7, s1, s);
}

__device__ __forceinline__ float cospoly_mag(double x2)
{
    double x4 = x2 * x2;
    double c2 = fma(x2, C4_D, C3_D);
    double c1 = fma(x2, C1_D, C0_D);
    double x6 = x4 * x2;
    double c  = fma(x4, C2_D, c1);
    return (float)fma(x6, c2, c);
}

__device__ __forceinline__ float sign_xor(float v, uint32_t bit31)
{
    return __uint_as_float(__float_as_uint(v) ^ bit31);
}

// Branchless glibc sinf+cosf, valid (bit-exact) for |y| < 120 — guaranteed
// for this bounded-energy system. For |y| < pi/4 the reduction yields n=0,
// xr=x, reproducing the glibc fast paths bitwise (incl. tiny |y| < 2^-12).
__device__ __forceinline__ void glibc_sincosf(float y, float* so, float* co)
{
    double x = (double)y;

    double r  = x * HPI_INV_D;
    int    n  = __double2int_rn(r);   // fcvtns (ties-to-even)
    double rr = (double)n;
    double xr = fma(-rr, HPI_D, x);

    double x2 = xr * xr;
    float  sm = sinpoly_mag(xr, x2);
    float  cm = cospoly_mag(x2);

    int odd = n & 1;
    float smag = odd ? cm : sm;
    float cmag = odd ? sm : cm;
    *so = sign_xor(smag, ((uint32_t)(n & 2)) << 30);
    *co = sign_xor(cmag, ((uint32_t)((n + 1) & 2)) << 30);
}

__device__ __forceinline__ float glibc_cosf(float y)
{
    double x = (double)y;

    double r  = x * HPI_INV_D;
    int    n  = __double2int_rn(r);
    double rr = (double)n;
    double xr = fma(-rr, HPI_D, x);

    double x2 = xr * xr;
    float  sm = sinpoly_mag(xr, x2);
    float  cm = cospoly_mag(x2);

    float cmag = (n & 1) ? sm : cm;
    return sign_xor(cmag, ((uint32_t)((n + 1) & 2)) << 30);
}

// ---- Hamiltonian with aarch64-backend fusion pattern ----
__device__ __forceinline__ float ham_f(float p1, float p2,
                                       float s, float c,
                                       float c1, float c2)
{
    float denom = __fmul_rn(2.0f, fmaf(s, s, 1.0f));
    float t2    = __fmul_rn(2.0f, __fmul_rn(p2, p2));
    float t3    = __fmul_rn(__fmul_rn(2.0f, p1), p2);
    float num   = fmaf(-t3, c, fmaf(p1, p1, t2));
    float T     = __fdiv_rn(num, denom);
    float vw    = __fadd_rn(__fsub_rn(1.0f, c1), __fsub_rn(1.0f, c2));
    return fmaf(10.0f, vw, T);
}

__device__ __forceinline__ void grads_q(float q1, float q2, float p1, float p2,
                                        float c1b, float c2b,
                                        float* g1, float* g2)
{
    float sa, ca, sbq, cbq, sc, cc, sd, cd;

    float q1p = __fadd_rn(q1, EPS_F);
    float q1m = __fsub_rn(q1, EPS_F);
    float q2p = __fadd_rn(q2, EPS_F);
    float q2m = __fsub_rn(q2, EPS_F);

    glibc_sincosf(__fsub_rn(q1p, q2), &sa, &ca);
    glibc_sincosf(__fsub_rn(q1m, q2), &sbq, &cbq);
    glibc_sincosf(__fsub_rn(q1, q2p), &sc, &cc);
    glibc_sincosf(__fsub_rn(q1, q2m), &sd, &cd);
    float cq1p = glibc_cosf(q1p);
    float cq1m = glibc_cosf(q1m);
    float cq2p = glibc_cosf(q2p);
    float cq2m = glibc_cosf(q2m);

    float Hp1 = ham_f(p1, p2, sa, ca, cq1p, c2b);
    float Hm1 = ham_f(p1, p2, sbq, cbq, cq1m, c2b);
    *g1 = __fdiv_rn(__fsub_rn(Hp1, Hm1), TWO_EPS_F);

    float Hp2 = ham_f(p1, p2, sc, cc, c1b, cq2p);
    float Hm2 = ham_f(p1, p2, sd, cd, c1b, cq2m);
    *g2 = __fdiv_rn(__fsub_rn(Hp2, Hm2), TWO_EPS_F);
}

__device__ __forceinline__ void grads_p(float p1, float p2,
                                        float s, float c, float c1, float c2,
                                        float* g1, float* g2)
{
    float Hp1 = ham_f(__fadd_rn(p1, EPS_F), p2, s, c, c1, c2);
    float Hm1 = ham_f(__fsub_rn(p1, EPS_F), p2, s, c, c1, c2);
    *g1 = __fdiv_rn(__fsub_rn(Hp1, Hm1), TWO_EPS_F);

    float Hp2 = ham_f(p1, __fadd_rn(p2, EPS_F), s, c, c1, c2);
    float Hm2 = ham_f(p1, __fsub_rn(p2, EPS_F), s, c, c1, c2);
    *g2 = __fdiv_rn(__fsub_rn(Hp2, Hm2), TWO_EPS_F);
}

__device__ __forceinline__ float anorm(float th)
{
    float t = __fadd_rn(th, PI_F);
    float r = fmodf(t, TWO_PI_F);
    if (r < 0.0f) r = __fadd_rn(r, TWO_PI_F);
    return __fsub_rn(r, PI_F);
}

__global__ void __launch_bounds__(128, 4)
imagination_mpc_kernel(const float* __restrict__ q0,
                       const float* __restrict__ p0,
                       const float* __restrict__ actions,
                       const float* __restrict__ target,
                       float* __restrict__ out,
                       int n)
{
    int h = n >> 1;                       // trajectories per stream
    int i = blockIdx.x * blockDim.x + threadIdx.x;
    if (i >= h) return;

    int idx[2] = { i, i + h };            // two independent trajectories

    float q1[2], q2[2], p1[2], p2[2];
    float sb[2], cb[2], c1b[2], c2b[2];
    float run[2];
    const float* arow[2];

    float tg1 = target[0], tg2 = target[1];

#pragma unroll
    for (int j = 0; j < 2; j++) {
        q1[j] = q0[2 * idx[j]];     q2[j] = q0[2 * idx[j] + 1];
        p1[j] = p0[2 * idx[j]];     p2[j] = p0[2 * idx[j] + 1];
        arow[j] = actions + (long long)idx[j] * T_STEPS;
        glibc_sincosf(__fsub_rn(q1[j], q2[j]), &sb[j], &cb[j]);
        c1b[j] = glibc_cosf(q1[j]);
        c2b[j] = glibc_cosf(q2[j]);
        run[j] = 0.0f;
    }

#pragma unroll 1
    for (int t = 0; t < T_STEPS; t++) {
        float a[2];
#pragma unroll
        for (int j = 0; j < 2; j++) a[j] = __ldg(&arow[j][t]);

        // ---- running cost ----
#pragma unroll
        for (int j = 0; j < 2; j++) {
            float e1  = anorm(__fsub_rn(q1[j], tg1));
            float e2  = anorm(__fsub_rn(q2[j], tg2));
            float pos = fmaf(e1, e1, __fmul_rn(e2, e2));
            float vel = fmaf(p1[j], p1[j], __fmul_rn(p2[j], p2[j]));
            float asq = __fmul_rn(a[j], a[j]);
            float term_t = fmaf(0.01f, asq, __fadd_rn(pos, vel));
            run[j] = __fadd_rn(run[j], term_t);
        }

        // ---- symplectic step (phases interleaved across both chains) ----
        float gq1[2], gq2[2], gp1[2], gp2[2];
#pragma unroll
        for (int j = 0; j < 2; j++)
            grads_q(q1[j], q2[j], p1[j], p2[j], c1b[j], c2b[j], &gq1[j], &gq2[j]);
#pragma unroll
        for (int j = 0; j < 2; j++)
            grads_p(p1[j], p2[j], sb[j], cb[j], c1b[j], c2b[j], &gp1[j], &gp2[j]);

        float ph1[2], ph2[2];
#pragma unroll
        for (int j = 0; j < 2; j++) {
            ph1[j] = fmaf(-HALF_DT_FR_F, gp1[j], fmaf(-HALF_DT_F, gq1[j], p1[j]));
            ph2[j] = fmaf(-HALF_DT_FR_F, gp2[j], fmaf(-HALF_DT_F, gq2[j], p2[j]));
        }

        float gm1[2], gm2[2];
#pragma unroll
        for (int j = 0; j < 2; j++)
            grads_p(ph1[j], ph2[j], sb[j], cb[j], c1b[j], c2b[j], &gm1[j], &gm2[j]);

        float qn1[2], qn2[2];
#pragma unroll
        for (int j = 0; j < 2; j++) {
            qn1[j] = fmaf(DT_F, gm1[j], q1[j]);
            qn2[j] = fmaf(DT_F, gm2[j], q2[j]);
        }

        float sbn[2], cbn[2], c1n[2], c2n[2];
#pragma unroll
        for (int j = 0; j < 2; j++) {
            glibc_sincosf(__fsub_rn(qn1[j], qn2[j]), &sbn[j], &cbn[j]);
            c1n[j] = glibc_cosf(qn1[j]);
            c2n[j] = glibc_cosf(qn2[j]);
        }

        float hq1[2], hq2[2], hp1[2], hp2[2];
#pragma unroll
        for (int j = 0; j < 2; j++)
            grads_q(qn1[j], qn2[j], ph1[j], ph2[j], c1n[j], c2n[j], &hq1[j], &hq2[j]);
#pragma unroll
        for (int j = 0; j < 2; j++)
            grads_p(ph1[j], ph2[j], sbn[j], cbn[j], c1n[j], c2n[j], &hp1[j], &hp2[j]);

#pragma unroll
        for (int j = 0; j < 2; j++) {
            float pn1 = fmaf(-HALF_DT_FR_F, hp1[j], fmaf(-HALF_DT_F, hq1[j], ph1[j]));
            float pn2 = fmaf(-HALF_DT_FR_F, hp2[j], fmaf(-HALF_DT_F, hq2[j], ph2[j]));
            pn2 = fmaf(a[j], DT_F, pn2);

            q1[j] = qn1[j]; q2[j] = qn2[j]; p1[j] = pn1; p2[j] = pn2;
            sb[j] = sbn[j]; cb[j] = cbn[j]; c1b[j] = c1n[j]; c2b[j] = c2n[j];
        }
    }

    // ---- terminal cost ----
#pragma unroll
    for (int j = 0; j < 2; j++) {
        float e1 = anorm(__fsub_rn(q1[j], tg1));
        float e2 = anorm(__fsub_rn(q2[j], tg2));
        float pos_sum = fmaf(e2, e2, __fmul_rn(e1, e1));
        float vel_sum = fmaf(p2[j], p2[j], __fmul_rn(p1[j], p1[j]));
        float term = fmaf(10.0f, pos_sum, vel_sum);
        out[idx[j]] = __fadd_rn(run[j], term);
    }
}

extern "C" void kernel_launch(void* const* d_in, const int* in_sizes, int n_in,
                              void* d_out, int out_size)
{
    const float* q0      = (const float*)d_in[0];
    const float* p0      = (const float*)d_in[1];
    const float* actions = (const float*)d_in[2];
    const float* target  = (const float*)d_in[3];
    float* out = (float*)d_out;

    int n = in_sizes[0] / 2;
    int h = n / 2;                         // two trajectories per thread
    int threads = 128;
    int blocks = (h + threads - 1) / threads;
    imagination_mpc_kernel<<<blocks, threads>>>(q0, p0, actions, target, out, n);
}

// round 11
// speedup vs baseline: 1.8723x; 1.8702x over previous
#include <cuda_runtime.h>
#include <stdint.h>

// ---------------------------------------------------------------------------
// ImaginationMPCV2 — bit-exact to jax on Grace CPU (aarch64): XLA:CPU strict
// middle-end + backend FPOpFusion::Fast, trig = glibc optimized-routines
// sinf/cosf (TOINT_INTRINSICS), ported bit-exactly.
//
// R11 perf changes (bit-preserving):
//  * Trig cache across the step boundary: call-3 ham_grads (at q_new) and the
//    NEXT step's call-1 ham_grads evaluate trig at identical inputs -> compute
//    once. Per-step trig: 19 evals -> 11.
//  * All 11 evals per step are independent and batched in one unrolled array
//    loop -> ptxas interleaves 11 identical f64 chains (latency hiding).
//  * Back to 1 trajectory/thread (R9's 2-traj was an occupancy wash).
// ---------------------------------------------------------------------------

#define EPS_F          1e-5f
#define TWO_EPS_F      2e-5f
#define DT_F           0.02f
#define HALF_DT_F      0.01f
#define HALF_DT_FR_F   0.001f
#define PI_F           3.14159265358979323846f
#define TWO_PI_F       6.28318530717958647692f
#define T_STEPS        100

// ---- glibc sincosf constants (optimized-routines, table entry 0) ----
#define HPI_INV_D  0x1.45F306DC9C883p-1   // 2/pi
#define HPI_D      0x1.921FB54442D18p0    // pi/2
#define S1_D      -0x1.555545995a603p-3
#define S2_D       0x1.1107605230bc4p-7
#define S3_D      -0x1.994eb3774cf24p-13
#define C0_D       0x1p0
#define C1_D      -0x1.ffffffd0c621cp-2
#define C2_D       0x1.55553e1068f19p-5
#define C3_D      -0x1.6c087e89a359dp-10
#define C4_D       0x1.99343027bf8c3p-16

__device__ __forceinline__ float sinpoly_mag(double xr, double x2)
{
    double x3 = xr * x2;
    double s1 = fma(x2, S3_D, S2_D);
    double x7 = x3 * x2;
    double s  = fma(x3, S1_D, xr);
    return (float)fma(x7, s1, s);
}

__device__ __forceinline__ float cospoly_mag(double x2)
{
    double x4 = x2 * x2;
    double c2 = fma(x2, C4_D, C3_D);
    double c1 = fma(x2, C1_D, C0_D);
    double x6 = x4 * x2;
    double c  = fma(x4, C2_D, c1);
    return (float)fma(x6, c2, c);
}

__device__ __forceinline__ float sign_xor(float v, uint32_t bit31)
{
    return __uint_as_float(__float_as_uint(v) ^ bit31);
}

// Branchless glibc sinf+cosf, bit-exact for |y| < 120 (guaranteed here).
// For |y| < pi/4 the reduction yields n=0, xr=x -> glibc fast paths bitwise.
__device__ __forceinline__ void glibc_sincosf(float y, float* so, float* co)
{
    double x = (double)y;

    double r  = x * HPI_INV_D;
    int    n  = __double2int_rn(r);   // fcvtns (ties-to-even)
    double rr = (double)n;
    double xr = fma(-rr, HPI_D, x);

    double x2 = xr * xr;
    float  sm = sinpoly_mag(xr, x2);
    float  cm = cospoly_mag(x2);

    int odd = n & 1;
    float smag = odd ? cm : sm;
    float cmag = odd ? sm : cm;
    *so = sign_xor(smag, ((uint32_t)(n & 2)) << 30);
    *co = sign_xor(cmag, ((uint32_t)((n + 1) & 2)) << 30);
}

// ---- Hamiltonian with aarch64-backend fusion pattern ----
__device__ __forceinline__ float ham_f(float p1, float p2,
                                       float s, float c,
                                       float c1, float c2)
{
    float denom = __fmul_rn(2.0f, fmaf(s, s, 1.0f));
    float t2    = __fmul_rn(2.0f, __fmul_rn(p2, p2));
    float t3    = __fmul_rn(__fmul_rn(2.0f, p1), p2);
    float num   = fmaf(-t3, c, fmaf(p1, p1, t2));
    float T     = __fdiv_rn(num, denom);
    float vw    = __fadd_rn(__fsub_rn(1.0f, c1), __fsub_rn(1.0f, c2));
    return fmaf(10.0f, vw, T);
}

// Trig cache for one configuration q = (q1, q2):
//  [0]  sincos(q1-q2)        -> sb, cb       (base)
//  [1]  cos(q1)              -> c1b
//  [2]  cos(q2)              -> c2b
//  [3]  sincos(q1p-q2)       -> sa, ca       (q1+eps)
//  [4]  sincos(q1m-q2)       -> sbq, cbq     (q1-eps)
//  [5]  sincos(q1-q2p)       -> sc, cc       (q2+eps)
//  [6]  sincos(q1-q2m)       -> sd, cd       (q2-eps)
//  [7]  cos(q1p)             -> cq1p
//  [8]  cos(q1m)             -> cq1m
//  [9]  cos(q2p)             -> cq2p
//  [10] cos(q2m)             -> cq2m
struct Trig {
    float s[11];
    float c[11];
};

// Batched: 11 independent unified sincos chains, unrolled for ILP.
__device__ __forceinline__ void trig_batch(float q1, float q2, Trig* T)
{
    float args[11];
    float q1p = __fadd_rn(q1, EPS_F);
    float q1m = __fsub_rn(q1, EPS_F);
    float q2p = __fadd_rn(q2, EPS_F);
    float q2m = __fsub_rn(q2, EPS_F);

    args[0]  = __fsub_rn(q1, q2);
    args[1]  = q1;
    args[2]  = q2;
    args[3]  = __fsub_rn(q1p, q2);
    args[4]  = __fsub_rn(q1m, q2);
    args[5]  = __fsub_rn(q1, q2p);
    args[6]  = __fsub_rn(q1, q2m);
    args[7]  = q1p;
    args[8]  = q1m;
    args[9]  = q2p;
    args[10] = q2m;

#pragma unroll
    for (int k = 0; k < 11; k++) {
        glibc_sincosf(args[k], &T->s[k], &T->c[k]);
    }
}

// dH/dq via cached trig (pure f32).
__device__ __forceinline__ void grads_q_cached(const Trig* T,
                                               float p1, float p2,
                                               float* g1, float* g2)
{
    float Hp1 = ham_f(p1, p2, T->s[3], T->c[3], T->c[7], T->c[2]);
    float Hm1 = ham_f(p1, p2, T->s[4], T->c[4], T->c[8], T->c[2]);
    *g1 = __fdiv_rn(__fsub_rn(Hp1, Hm1), TWO_EPS_F);

    float Hp2 = ham_f(p1, p2, T->s[5], T->c[5], T->c[1], T->c[9]);
    float Hm2 = ham_f(p1, p2, T->s[6], T->c[6], T->c[1], T->c[10]);
    *g2 = __fdiv_rn(__fsub_rn(Hp2, Hm2), TWO_EPS_F);
}

// dH/dp via base trig (pure f32).
__device__ __forceinline__ void grads_p_cached(const Trig* T,
                                               float p1, float p2,
                                               float* g1, float* g2)
{
    float s = T->s[0], c = T->c[0], c1 = T->c[1], c2 = T->c[2];

    float Hp1 = ham_f(__fadd_rn(p1, EPS_F), p2, s, c, c1, c2);
    float Hm1 = ham_f(__fsub_rn(p1, EPS_F), p2, s, c, c1, c2);
    *g1 = __fdiv_rn(__fsub_rn(Hp1, Hm1), TWO_EPS_F);

    float Hp2 = ham_f(p1, __fadd_rn(p2, EPS_F), s, c, c1, c2);
    float Hm2 = ham_f(p1, __fsub_rn(p2, EPS_F), s, c, c1, c2);
    *g2 = __fdiv_rn(__fsub_rn(Hp2, Hm2), TWO_EPS_F);
}

__device__ __forceinline__ float anorm(float th)
{
    float t = __fadd_rn(th, PI_F);
    float r = fmodf(t, TWO_PI_F);
    if (r < 0.0f) r = __fadd_rn(r, TWO_PI_F);
    return __fsub_rn(r, PI_F);
}

__global__ void __launch_bounds__(128, 4)
imagination_mpc_kernel(const float* __restrict__ q0,
                       const float* __restrict__ p0,
                       const float* __restrict__ actions,
                       const float* __restrict__ target,
                       float* __restrict__ out,
                       int n)
{
    int i = blockIdx.x * blockDim.x + threadIdx.x;
    if (i >= n) return;

    float q1 = q0[2 * i], q2 = q0[2 * i + 1];
    float p1 = p0[2 * i], p2 = p0[2 * i + 1];
    float tg1 = target[0], tg2 = target[1];
    const float* arow = actions + (long long)i * T_STEPS;

    // Trig cache at the current q (serves call-1 grads_q + grads_p).
    Trig T;
    trig_batch(q1, q2, &T);

    float run = 0.0f;

#pragma unroll 1
    for (int t = 0; t < T_STEPS; t++) {
        float a = __ldg(&arow[t]);

        // ---- running cost at state index t ----
        {
            float e1  = anorm(__fsub_rn(q1, tg1));
            float e2  = anorm(__fsub_rn(q2, tg2));
            float pos = fmaf(e1, e1, __fmul_rn(e2, e2));
            float vel = fmaf(p1, p1, __fmul_rn(p2, p2));
            float asq = __fmul_rn(a, a);
            float term_t = fmaf(0.01f, asq, __fadd_rn(pos, vel));
            run = __fadd_rn(run, term_t);
        }

        // ---- call 1: full grads at (q, p) — all from cache (f32 only) ----
        float gq1, gq2, gp1, gp2;
        grads_q_cached(&T, p1, p2, &gq1, &gq2);
        grads_p_cached(&T, p1, p2, &gp1, &gp2);

        float ph1 = fmaf(-HALF_DT_FR_F, gp1, fmaf(-HALF_DT_F, gq1, p1));
        float ph2 = fmaf(-HALF_DT_FR_F, gp2, fmaf(-HALF_DT_F, gq2, p2));

        // ---- call 2: dH/dp at (q, p_half) — same cache ----
        float gm1, gm2;
        grads_p_cached(&T, ph1, ph2, &gm1, &gm2);

        float qn1 = fmaf(DT_F, gm1, q1);
        float qn2 = fmaf(DT_F, gm2, q2);

        // ---- ONE trig batch per step: everything at q_new.
        //      Serves call 3 AND next iteration's call 1/2 (identical inputs
        //      in the reference -> bitwise-safe reuse). ----
        trig_batch(qn1, qn2, &T);

        // ---- call 3: full grads at (q_new, p_half) ----
        float hq1, hq2, hp1, hp2;
        grads_q_cached(&T, ph1, ph2, &hq1, &hq2);
        grads_p_cached(&T, ph1, ph2, &hp1, &hp2);

        float pn1 = fmaf(-HALF_DT_FR_F, hp1, fmaf(-HALF_DT_F, hq1, ph1));
        float pn2 = fmaf(-HALF_DT_FR_F, hp2, fmaf(-HALF_DT_F, hq2, ph2));
        pn2 = fmaf(a, DT_F, pn2);

        q1 = qn1; q2 = qn2; p1 = pn1; p2 = pn2;
    }

    // ---- terminal cost (reduce-based sums -> second-operand fusion) ----
    float e1 = anorm(__fsub_rn(q1, tg1));
    float e2 = anorm(__fsub_rn(q2, tg2));
    float pos_sum = fmaf(e2, e2, __fmul_rn(e1, e1));
    float vel_sum = fmaf(p2, p2, __fmul_rn(p1, p1));
    float term = fmaf(10.0f, pos_sum, vel_sum);

    out[i] = __fadd_rn(run, term);
}

extern "C" void kernel_launch(void* const* d_in, const int* in_sizes, int n_in,
                              void* d_out, int out_size)
{
    const float* q0      = (const float*)d_in[0];
    const float* p0      = (const float*)d_in[1];
    const float* actions = (const float*)d_in[2];
    const float* target  = (const float*)d_in[3];
    float* out = (float*)d_out;

    int n = in_sizes[0] / 2;
    int threads = 128;
    int blocks = (n + threads - 1) / threads;
    imagination_mpc_kernel<<<blocks, threads>>>(q0, p0, actions, target, out, n);
}

// round 12
// speedup vs baseline: 1.8733x; 1.0006x over previous
#include <cuda_runtime.h>
#include <stdint.h>

// ---------------------------------------------------------------------------
// ImaginationMPCV2 — bit-exact to jax on Grace CPU (aarch64): XLA:CPU strict
// middle-end + backend FPOpFusion::Fast, trig = glibc optimized-routines
// sinf/cosf (TOINT_INTRINSICS), ported bit-exactly.
//
// R11 perf changes (bit-preserving):
//  * Trig cache across the step boundary: call-3 ham_grads (at q_new) and the
//    NEXT step's call-1 ham_grads evaluate trig at identical inputs -> compute
//    once. Per-step trig: 19 evals -> 11.
//  * All 11 evals per step are independent and batched in one unrolled array
//    loop -> ptxas interleaves 11 identical f64 chains (latency hiding).
//  * Back to 1 trajectory/thread (R9's 2-traj was an occupancy wash).
// ---------------------------------------------------------------------------

#define EPS_F          1e-5f
#define TWO_EPS_F      2e-5f
#define DT_F           0.02f
#define HALF_DT_F      0.01f
#define HALF_DT_FR_F   0.001f
#define PI_F           3.14159265358979323846f
#define TWO_PI_F       6.28318530717958647692f
#define T_STEPS        100

// ---- glibc sincosf constants (optimized-routines, table entry 0) ----
#define HPI_INV_D  0x1.45F306DC9C883p-1   // 2/pi
#define HPI_D      0x1.921FB54442D18p0    // pi/2
#define S1_D      -0x1.555545995a603p-3
#define S2_D       0x1.1107605230bc4p-7
#define S3_D      -0x1.994eb3774cf24p-13
#define C0_D       0x1p0
#define C1_D      -0x1.ffffffd0c621cp-2
#define C2_D       0x1.55553e1068f19p-5
#define C3_D      -0x1.6c087e89a359dp-10
#define C4_D       0x1.99343027bf8c3p-16

__device__ __forceinline__ float sinpoly_mag(double xr, double x2)
{
    double x3 = xr * x2;
    double s1 = fma(x2, S3_D, S2_D);
    double x7 = x3 * x2;
    double s  = fma(x3, S1_D, xr);
    return (float)fma(x7, s1, s);
}

__device__ __forceinline__ float cospoly_mag(double x2)
{
    double x4 = x2 * x2;
    double c2 = fma(x2, C4_D, C3_D);
    double c1 = fma(x2, C1_D, C0_D);
    double x6 = x4 * x2;
    double c  = fma(x4, C2_D, c1);
    return (float)fma(x6, c2, c);
}

__device__ __forceinline__ float sign_xor(float v, uint32_t bit31)
{
    return __uint_as_float(__float_as_uint(v) ^ bit31);
}

// Branchless glibc sinf+cosf, bit-exact for |y| < 120 (guaranteed here).
// For |y| < pi/4 the reduction yields n=0, xr=x -> glibc fast paths bitwise.
__device__ __forceinline__ void glibc_sincosf(float y, float* so, float* co)
{
    double x = (double)y;

    double r  = x * HPI_INV_D;
    int    n  = __double2int_rn(r);   // fcvtns (ties-to-even)
    double rr = (double)n;
    double xr = fma(-rr, HPI_D, x);

    double x2 = xr * xr;
    float  sm = sinpoly_mag(xr, x2);
    float  cm = cospoly_mag(x2);

    int odd = n & 1;
    float smag = odd ? cm : sm;
    float cmag = odd ? sm : cm;
    *so = sign_xor(smag, ((uint32_t)(n & 2)) << 30);
    *co = sign_xor(cmag, ((uint32_t)((n + 1) & 2)) << 30);
}

// ---- Hamiltonian with aarch64-backend fusion pattern ----
__device__ __forceinline__ float ham_f(float p1, float p2,
                                       float s, float c,
                                       float c1, float c2)
{
    float denom = __fmul_rn(2.0f, fmaf(s, s, 1.0f));
    float t2    = __fmul_rn(2.0f, __fmul_rn(p2, p2));
    float t3    = __fmul_rn(__fmul_rn(2.0f, p1), p2);
    float num   = fmaf(-t3, c, fmaf(p1, p1, t2));
    float T     = __fdiv_rn(num, denom);
    float vw    = __fadd_rn(__fsub_rn(1.0f, c1), __fsub_rn(1.0f, c2));
    return fmaf(10.0f, vw, T);
}

// Trig cache for one configuration q = (q1, q2):
//  [0]  sincos(q1-q2)        -> sb, cb       (base)
//  [1]  cos(q1)              -> c1b
//  [2]  cos(q2)              -> c2b
//  [3]  sincos(q1p-q2)       -> sa, ca       (q1+eps)
//  [4]  sincos(q1m-q2)       -> sbq, cbq     (q1-eps)
//  [5]  sincos(q1-q2p)       -> sc, cc       (q2+eps)
//  [6]  sincos(q1-q2m)       -> sd, cd       (q2-eps)
//  [7]  cos(q1p)             -> cq1p
//  [8]  cos(q1m)             -> cq1m
//  [9]  cos(q2p)             -> cq2p
//  [10] cos(q2m)             -> cq2m
struct Trig {
    float s[11];
    float c[11];
};

// Batched: 11 independent unified sincos chains, unrolled for ILP.
__device__ __forceinline__ void trig_batch(float q1, float q2, Trig* T)
{
    float args[11];
    float q1p = __fadd_rn(q1, EPS_F);
    float q1m = __fsub_rn(q1, EPS_F);
    float q2p = __fadd_rn(q2, EPS_F);
    float q2m = __fsub_rn(q2, EPS_F);

    args[0]  = __fsub_rn(q1, q2);
    args[1]  = q1;
    args[2]  = q2;
    args[3]  = __fsub_rn(q1p, q2);
    args[4]  = __fsub_rn(q1m, q2);
    args[5]  = __fsub_rn(q1, q2p);
    args[6]  = __fsub_rn(q1, q2m);
    args[7]  = q1p;
    args[8]  = q1m;
    args[9]  = q2p;
    args[10] = q2m;

#pragma unroll
    for (int k = 0; k < 11; k++) {
        glibc_sincosf(args[k], &T->s[k], &T->c[k]);
    }
}

// dH/dq via cached trig (pure f32).
__device__ __forceinline__ void grads_q_cached(const Trig* T,
                                               float p1, float p2,
                                               float* g1, float* g2)
{
    float Hp1 = ham_f(p1, p2, T->s[3], T->c[3], T->c[7], T->c[2]);
    float Hm1 = ham_f(p1, p2, T->s[4], T->c[4], T->c[8], T->c[2]);
    *g1 = __fdiv_rn(__fsub_rn(Hp1, Hm1), TWO_EPS_F);

    float Hp2 = ham_f(p1, p2, T->s[5], T->c[5], T->c[1], T->c[9]);
    float Hm2 = ham_f(p1, p2, T->s[6], T->c[6], T->c[1], T->c[10]);
    *g2 = __fdiv_rn(__fsub_rn(Hp2, Hm2), TWO_EPS_F);
}

// dH/dp via base trig (pure f32).
__device__ __forceinline__ void grads_p_cached(const Trig* T,
                                               float p1, float p2,
                                               float* g1, float* g2)
{
    float s = T->s[0], c = T->c[0], c1 = T->c[1], c2 = T->c[2];

    float Hp1 = ham_f(__fadd_rn(p1, EPS_F), p2, s, c, c1, c2);
    float Hm1 = ham_f(__fsub_rn(p1, EPS_F), p2, s, c, c1, c2);
    *g1 = __fdiv_rn(__fsub_rn(Hp1, Hm1), TWO_EPS_F);

    float Hp2 = ham_f(p1, __fadd_rn(p2, EPS_F), s, c, c1, c2);
    float Hm2 = ham_f(p1, __fsub_rn(p2, EPS_F), s, c, c1, c2);
    *g2 = __fdiv_rn(__fsub_rn(Hp2, Hm2), TWO_EPS_F);
}

__device__ __forceinline__ float anorm(float th)
{
    float t = __fadd_rn(th, PI_F);
    float r = fmodf(t, TWO_PI_F);
    if (r < 0.0f) r = __fadd_rn(r, TWO_PI_F);
    return __fsub_rn(r, PI_F);
}

__global__ void __launch_bounds__(128, 4)
imagination_mpc_kernel(const float* __restrict__ q0,
                       const float* __restrict__ p0,
                       const float* __restrict__ actions,
                       const float* __restrict__ target,
                       float* __restrict__ out,
                       int n)
{
    int i = blockIdx.x * blockDim.x + threadIdx.x;
    if (i >= n) return;

    float q1 = q0[2 * i], q2 = q0[2 * i + 1];
    float p1 = p0[2 * i], p2 = p0[2 * i + 1];
    float tg1 = target[0], tg2 = target[1];
    const float* arow = actions + (long long)i * T_STEPS;

    // Trig cache at the current q (serves call-1 grads_q + grads_p).
    Trig T;
    trig_batch(q1, q2, &T);

    float run = 0.0f;

#pragma unroll 1
    for (int t = 0; t < T_STEPS; t++) {
        float a = __ldg(&arow[t]);

        // ---- running cost at state index t ----
        {
            float e1  = anorm(__fsub_rn(q1, tg1));
            float e2  = anorm(__fsub_rn(q2, tg2));
            float pos = fmaf(e1, e1, __fmul_rn(e2, e2));
            float vel = fmaf(p1, p1, __fmul_rn(p2, p2));
            float asq = __fmul_rn(a, a);
            float term_t = fmaf(0.01f, asq, __fadd_rn(pos, vel));
            run = __fadd_rn(run, term_t);
        }

        // ---- call 1: full grads at (q, p) — all from cache (f32 only) ----
        float gq1, gq2, gp1, gp2;
        grads_q_cached(&T, p1, p2, &gq1, &gq2);
        grads_p_cached(&T, p1, p2, &gp1, &gp2);

        float ph1 = fmaf(-HALF_DT_FR_F, gp1, fmaf(-HALF_DT_F, gq1, p1));
        float ph2 = fmaf(-HALF_DT_FR_F, gp2, fmaf(-HALF_DT_F, gq2, p2));

        // ---- call 2: dH/dp at (q, p_half) — same cache ----
        float gm1, gm2;
        grads_p_cached(&T, ph1, ph2, &gm1, &gm2);

        float qn1 = fmaf(DT_F, gm1, q1);
        float qn2 = fmaf(DT_F, gm2, q2);

        // ---- ONE trig batch per step: everything at q_new.
        //      Serves call 3 AND next iteration's call 1/2 (identical inputs
        //      in the reference -> bitwise-safe reuse). ----
        trig_batch(qn1, qn2, &T);

        // ---- call 3: full grads at (q_new, p_half) ----
        float hq1, hq2, hp1, hp2;
        grads_q_cached(&T, ph1, ph2, &hq1, &hq2);
        grads_p_cached(&T, ph1, ph2, &hp1, &hp2);

        float pn1 = fmaf(-HALF_DT_FR_F, hp1, fmaf(-HALF_DT_F, hq1, ph1));
        float pn2 = fmaf(-HALF_DT_FR_F, hp2, fmaf(-HALF_DT_F, hq2, ph2));
        pn2 = fmaf(a, DT_F, pn2);

        q1 = qn1; q2 = qn2; p1 = pn1; p2 = pn2;
    }

    // ---- terminal cost (reduce-based sums -> second-operand fusion) ----
    float e1 = anorm(__fsub_rn(q1, tg1));
    float e2 = anorm(__fsub_rn(q2, tg2));
    float pos_sum = fmaf(e2, e2, __fmul_rn(e1, e1));
    float vel_sum = fmaf(p2, p2, __fmul_rn(p1, p1));
    float term = fmaf(10.0f, pos_sum, vel_sum);

    out[i] = __fadd_rn(run, term);
}

extern "C" void kernel_launch(void* const* d_in, const int* in_sizes, int n_in,
                              void* d_out, int out_size)
{
    const float* q0      = (const float*)d_in[0];
    const float* p0      = (const float*)d_in[1];
    const float* actions = (const float*)d_in[2];
    const float* target  = (const float*)d_in[3];
    float* out = (float*)d_out;

    int n = in_sizes[0] / 2;
    int threads = 128;
    int blocks = (n + threads - 1) / threads;
    imagination_mpc_kernel<<<blocks, threads>>>(q0, p0, actions, target, out, n);
}

// round 17
// speedup vs baseline: 1.8735x; 1.0001x over previous
#include <cuda_runtime.h>
#include <stdint.h>

// ---------------------------------------------------------------------------
// ImaginationMPCV2 — bit-exact to jax on Grace CPU (aarch64): XLA:CPU strict
// middle-end + backend FPOpFusion::Fast, trig = glibc optimized-routines
// sinf/cosf (TOINT_INTRINSICS), ported bit-exactly.
//
// R13 perf changes (storage-only; all values bit-identical):
//  * Perturbation trig cache (12 floats) moved to shared memory
//    (conflict-free thread-column layout) -> frees ~25+ registers.
//  * Base trig (4 floats, hottest) stays in registers.
//  * __launch_bounds__(128, 6): <=85 regs -> 6 CTAs/SM (occ 23% -> ~35%).
// ---------------------------------------------------------------------------

#define EPS_F          1e-5f
#define TWO_EPS_F      2e-5f
#define DT_F           0.02f
#define HALF_DT_F      0.01f
#define HALF_DT_FR_F   0.001f
#define PI_F           3.14159265358979323846f
#define TWO_PI_F       6.28318530717958647692f
#define T_STEPS        100
#define BLOCK          128

// ---- glibc sincosf constants (optimized-routines, table entry 0) ----
#define HPI_INV_D  0x1.45F306DC9C883p-1   // 2/pi
#define HPI_D      0x1.921FB54442D18p0    // pi/2
#define S1_D      -0x1.555545995a603p-3
#define S2_D       0x1.1107605230bc4p-7
#define S3_D      -0x1.994eb3774cf24p-13
#define C0_D       0x1p0
#define C1_D      -0x1.ffffffd0c621cp-2
#define C2_D       0x1.55553e1068f19p-5
#define C3_D      -0x1.6c087e89a359dp-10
#define C4_D       0x1.99343027bf8c3p-16

__device__ __forceinline__ float sinpoly_mag(double xr, double x2)
{
    double x3 = xr * x2;
    double s1 = fma(x2, S3_D, S2_D);
    double x7 = x3 * x2;
    double s  = fma(x3, S1_D, xr);
    return (float)fma(x7, s1, s);
}

__device__ __forceinline__ float cospoly_mag(double x2)
{
    double x4 = x2 * x2;
    double c2 = fma(x2, C4_D, C3_D);
    double c1 = fma(x2, C1_D, C0_D);
    double x6 = x4 * x2;
    double c  = fma(x4, C2_D, c1);
    return (float)fma(x6, c2, c);
}

__device__ __forceinline__ float sign_xor(float v, uint32_t bit31)
{
    return __uint_as_float(__float_as_uint(v) ^ bit31);
}

// Branchless glibc sinf+cosf, bit-exact for |y| < 120 (guaranteed here).
__device__ __forceinline__ void glibc_sincosf(float y, float* so, float* co)
{
    double x = (double)y;

    double r  = x * HPI_INV_D;
    int    n  = __double2int_rn(r);   // fcvtns (ties-to-even)
    double rr = (double)n;
    double xr = fma(-rr, HPI_D, x);

    double x2 = xr * xr;
    float  sm = sinpoly_mag(xr, x2);
    float  cm = cospoly_mag(x2);

    int odd = n & 1;
    float smag = odd ? cm : sm;
    float cmag = odd ? sm : cm;
    *so = sign_xor(smag, ((uint32_t)(n & 2)) << 30);
    *co = sign_xor(cmag, ((uint32_t)((n + 1) & 2)) << 30);
}

// cos-only variant (sin select dead-coded; both polys still required).
__device__ __forceinline__ float glibc_cosf(float y)
{
    double x = (double)y;

    double r  = x * HPI_INV_D;
    int    n  = __double2int_rn(r);
    double rr = (double)n;
    double xr = fma(-rr, HPI_D, x);

    double x2 = xr * xr;
    float  sm = sinpoly_mag(xr, x2);
    float  cm = cospoly_mag(x2);

    float cmag = (n & 1) ? sm : cm;
    return sign_xor(cmag, ((uint32_t)((n + 1) & 2)) << 30);
}

// ---- Hamiltonian with aarch64-backend fusion pattern ----
__device__ __forceinline__ float ham_f(float p1, float p2,
                                       float s, float c,
                                       float c1, float c2)
{
    float denom = __fmul_rn(2.0f, fmaf(s, s, 1.0f));
    float t2    = __fmul_rn(2.0f, __fmul_rn(p2, p2));
    float t3    = __fmul_rn(__fmul_rn(2.0f, p1), p2);
    float num   = fmaf(-t3, c, fmaf(p1, p1, t2));
    float T     = __fdiv_rn(num, denom);
    float vw    = __fadd_rn(__fsub_rn(1.0f, c1), __fsub_rn(1.0f, c2));
    return fmaf(10.0f, vw, T);
}

// Shared-memory rows for the 12 perturbation trig values:
//  0: sin(q1p-q2)  1: sin(q1m-q2)  2: sin(q1-q2p)  3: sin(q1-q2m)
//  4: cos(q1p-q2)  5: cos(q1m-q2)  6: cos(q1-q2p)  7: cos(q1-q2m)
//  8: cos(q1p)     9: cos(q1m)    10: cos(q2p)    11: cos(q2m)
#define ROW_SA   0
#define ROW_SB   1
#define ROW_SC   2
#define ROW_SD   3
#define ROW_CA   4
#define ROW_CB   5
#define ROW_CC   6
#define ROW_CD   7
#define ROW_CQ1P 8
#define ROW_CQ1M 9
#define ROW_CQ2P 10
#define ROW_CQ2M 11

// One trig batch per q-configuration: base (regs) + 12 perturbation values
// (smem). 11 independent f64 chains for ptxas to interleave.
__device__ __forceinline__ void trig_batch(float q1, float q2,
                                           float* sb, float* cb,
                                           float* c1b, float* c2b,
                                           float (*P)[BLOCK], int tid)
{
    float q1p = __fadd_rn(q1, EPS_F);
    float q1m = __fsub_rn(q1, EPS_F);
    float q2p = __fadd_rn(q2, EPS_F);
    float q2m = __fsub_rn(q2, EPS_F);

    glibc_sincosf(__fsub_rn(q1, q2), sb, cb);
    *c1b = glibc_cosf(q1);
    *c2b = glibc_cosf(q2);

    float s, c;
    glibc_sincosf(__fsub_rn(q1p, q2), &s, &c);
    P[ROW_SA][tid] = s; P[ROW_CA][tid] = c;
    glibc_sincosf(__fsub_rn(q1m, q2), &s, &c);
    P[ROW_SB][tid] = s; P[ROW_CB][tid] = c;
    glibc_sincosf(__fsub_rn(q1, q2p), &s, &c);
    P[ROW_SC][tid] = s; P[ROW_CC][tid] = c;
    glibc_sincosf(__fsub_rn(q1, q2m), &s, &c);
    P[ROW_SD][tid] = s; P[ROW_CD][tid] = c;

    P[ROW_CQ1P][tid] = glibc_cosf(q1p);
    P[ROW_CQ1M][tid] = glibc_cosf(q1m);
    P[ROW_CQ2P][tid] = glibc_cosf(q2p);
    P[ROW_CQ2M][tid] = glibc_cosf(q2m);
}

// dH/dq via cached trig (perturbation values from smem, base cos from regs).
__device__ __forceinline__ void grads_q_cached(const float (*P)[BLOCK], int tid,
                                               float c1b, float c2b,
                                               float p1, float p2,
                                               float* g1, float* g2)
{
    float Hp1 = ham_f(p1, p2, P[ROW_SA][tid], P[ROW_CA][tid], P[ROW_CQ1P][tid], c2b);
    float Hm1 = ham_f(p1, p2, P[ROW_SB][tid], P[ROW_CB][tid], P[ROW_CQ1M][tid], c2b);
    *g1 = __fdiv_rn(__fsub_rn(Hp1, Hm1), TWO_EPS_F);

    float Hp2 = ham_f(p1, p2, P[ROW_SC][tid], P[ROW_CC][tid], c1b, P[ROW_CQ2P][tid]);
    float Hm2 = ham_f(p1, p2, P[ROW_SD][tid], P[ROW_CD][tid], c1b, P[ROW_CQ2M][tid]);
    *g2 = __fdiv_rn(__fsub_rn(Hp2, Hm2), TWO_EPS_F);
}

// dH/dp via base trig (registers only).
__device__ __forceinline__ void grads_p_cached(float sb, float cb,
                                               float c1b, float c2b,
                                               float p1, float p2,
                                               float* g1, float* g2)
{
    float Hp1 = ham_f(__fadd_rn(p1, EPS_F), p2, sb, cb, c1b, c2b);
    float Hm1 = ham_f(__fsub_rn(p1, EPS_F), p2, sb, cb, c1b, c2b);
    *g1 = __fdiv_rn(__fsub_rn(Hp1, Hm1), TWO_EPS_F);

    float Hp2 = ham_f(p1, __fadd_rn(p2, EPS_F), sb, cb, c1b, c2b);
    float Hm2 = ham_f(p1, __fsub_rn(p2, EPS_F), sb, cb, c1b, c2b);
    *g2 = __fdiv_rn(__fsub_rn(Hp2, Hm2), TWO_EPS_F);
}

__device__ __forceinline__ float anorm(float th)
{
    float t = __fadd_rn(th, PI_F);
    float r = fmodf(t, TWO_PI_F);
    if (r < 0.0f) r = __fadd_rn(r, TWO_PI_F);
    return __fsub_rn(r, PI_F);
}

__global__ void __launch_bounds__(BLOCK, 6)
imagination_mpc_kernel(const float* __restrict__ q0,
                       const float* __restrict__ p0,
                       const float* __restrict__ actions,
                       const float* __restrict__ target,
                       float* __restrict__ out,
                       int n)
{
    __shared__ float P[12][BLOCK];        // perturbation trig cache (6 KB)

    int tid = threadIdx.x;
    int i = blockIdx.x * BLOCK + tid;
    if (i >= n) return;

    float q1 = q0[2 * i], q2 = q0[2 * i + 1];
    float p1 = p0[2 * i], p2 = p0[2 * i + 1];
    float tg1 = target[0], tg2 = target[1];
    const float* arow = actions + (long long)i * T_STEPS;

    float sb, cb, c1b, c2b;
    trig_batch(q1, q2, &sb, &cb, &c1b, &c2b, P, tid);

    float run = 0.0f;

#pragma unroll 1
    for (int t = 0; t < T_STEPS; t++) {
        float a = __ldg(&arow[t]);

        // ---- running cost at state index t ----
        {
            float e1  = anorm(__fsub_rn(q1, tg1));
            float e2  = anorm(__fsub_rn(q2, tg2));
            float pos = fmaf(e1, e1, __fmul_rn(e2, e2));
            float vel = fmaf(p1, p1, __fmul_rn(p2, p2));
            float asq = __fmul_rn(a, a);
            float term_t = fmaf(0.01f, asq, __fadd_rn(pos, vel));
            run = __fadd_rn(run, term_t);
        }

        // ---- call 1: full grads at (q, p) — from cache ----
        float gq1, gq2, gp1, gp2;
        grads_q_cached(P, tid, c1b, c2b, p1, p2, &gq1, &gq2);
        grads_p_cached(sb, cb, c1b, c2b, p1, p2, &gp1, &gp2);

        float ph1 = fmaf(-HALF_DT_FR_F, gp1, fmaf(-HALF_DT_F, gq1, p1));
        float ph2 = fmaf(-HALF_DT_FR_F, gp2, fmaf(-HALF_DT_F, gq2, p2));

        // ---- call 2: dH/dp at (q, p_half) ----
        float gm1, gm2;
        grads_p_cached(sb, cb, c1b, c2b, ph1, ph2, &gm1, &gm2);

        float qn1 = fmaf(DT_F, gm1, q1);
        float qn2 = fmaf(DT_F, gm2, q2);

        // ---- ONE trig batch per step at q_new (serves call 3 + next call 1/2) ----
        trig_batch(qn1, qn2, &sb, &cb, &c1b, &c2b, P, tid);

        // ---- call 3: full grads at (q_new, p_half) ----
        float hq1, hq2, hp1, hp2;
        grads_q_cached(P, tid, c1b, c2b, ph1, ph2, &hq1, &hq2);
        grads_p_cached(sb, cb, c1b, c2b, ph1, ph2, &hp1, &hp2);

        float pn1 = fmaf(-HALF_DT_FR_F, hp1, fmaf(-HALF_DT_F, hq1, ph1));
        float pn2 = fmaf(-HALF_DT_FR_F, hp2, fmaf(-HALF_DT_F, hq2, ph2));
        pn2 = fmaf(a, DT_F, pn2);

        q1 = qn1; q2 = qn2; p1 = pn1; p2 = pn2;
    }

    // ---- terminal cost (reduce-based sums -> second-operand fusion) ----
    float e1 = anorm(__fsub_rn(q1, tg1));
    float e2 = anorm(__fsub_rn(q2, tg2));
    float pos_sum = fmaf(e2, e2, __fmul_rn(e1, e1));
    float vel_sum = fmaf(p2, p2, __fmul_rn(p1, p1));
    float term = fmaf(10.0f, pos_sum, vel_sum);

    out[i] = __fadd_rn(run, term);
}

extern "C" void kernel_launch(void* const* d_in, const int* in_sizes, int n_in,
                              void* d_out, int out_size)
{
    const float* q0      = (const float*)d_in[0];
    const float* p0      = (const float*)d_in[1];
    const float* actions = (const float*)d_in[2];
    const float* target  = (const float*)d_in[3];
    float* out = (float*)d_out;

    int n = in_sizes[0] / 2;
    int blocks = (n + BLOCK - 1) / BLOCK;
    imagination_mpc_kernel<<<blocks, BLOCK>>>(q0, p0, actions, target, out, n);
}